// round 14
// baseline (speedup 1.0000x reference)
#include <cuda_runtime.h>
#include <cuda_fp16.h>

// Problem constants
#define NB 8
#define NT 4096
#define ND 2048
#define NS 64
#define M_TOT (NB*NT)      // 32768 rows
#define NCHUNK 64          // scan chunks
#define CLEN   64          // steps per chunk (NCHUNK*CLEN == NT)

// ---------------- scratch (static __device__ — no allocations allowed) ----
__device__ float        g_a[(size_t)M_TOT*NS];        // 8 MB  gate  (fp32)
__device__ float        g_b[(size_t)M_TOT*NS];        // 8 MB  input (fp32)
__device__ __half       g_hs[(size_t)M_TOT*NS];       // 4 MB  states (fp16)
__device__ float        g_A[(size_t)NB*NCHUNK*NS];    // chunk gate products
__device__ float        g_E[(size_t)NB*NCHUNK*NS];    // chunk local end values
__device__ float        g_hin[(size_t)NB*NCHUNK*NS];  // chunk entry states

// ---------------- helpers -------------------------------------------------
__device__ __forceinline__ void mma16h(float c[4], const unsigned int a[4],
                                       const unsigned int b[2]) {
    asm volatile(
        "mma.sync.aligned.m16n8k16.row.col.f32.f16.f16.f32 "
        "{%0,%1,%2,%3},{%4,%5,%6,%7},{%8,%9},{%0,%1,%2,%3};"
        : "+f"(c[0]), "+f"(c[1]), "+f"(c[2]), "+f"(c[3])
        : "r"(a[0]), "r"(a[1]), "r"(a[2]), "r"(a[3]), "r"(b[0]), "r"(b[1]));
}

__device__ __forceinline__ unsigned int pack_h2(float lo, float hi) {
    __half2 h = __floats2half2_rn(lo, hi);
    return *reinterpret_cast<unsigned int*>(&h);
}

__device__ __forceinline__ void cpa16(void* sdst, const void* gsrc) {
    unsigned int sa = (unsigned int)__cvta_generic_to_shared(sdst);
    asm volatile("cp.async.cg.shared.global [%0], [%1], 16;"
                 :: "r"(sa), "l"(gsrc) : "memory");
}
__device__ __forceinline__ void cp_commit() {
    asm volatile("cp.async.commit_group;" ::: "memory");
}

// ---------------- kernel 1: a,b = tanh(x @ [Wa;Wb]^T + bias) --------------
// GEMM M=32768, N=128, K=2048. 128x128 blocks, BK=32, fp16 smem tiles.
// Tiles staged through registers: LDG.128 fp32 -> cvt -> STS fp16 (double
// buffered; LDG for tile k+1 overlaps mma of tile k). Fragments are direct
// uint loads from fp16 smem (out_kernel-proven pattern, no inner cvt).
// 8 warps in 2(m) x 4(n) grid, warp tile 64x32, fp16 m16n8k16 mma.
#define BK1  32
#define LDXH 40   // half stride: 20-word rows -> conflict-free fragments

__global__ void __launch_bounds__(256, 2)
proj_kernel(const float* __restrict__ x,
            const float* __restrict__ Wa, const float* __restrict__ Wb,
            const float* __restrict__ ba, const float* __restrict__ bb) {
    extern __shared__ char sm[];
    __half* Xh   = (__half*)sm;                          // [2][128][LDXH]
    __half* Wh   = (__half*)(sm + 2*128*LDXH*2);         // [2][128][LDXH]
    float*  bias = (float*)(sm + 4*128*LDXH*2);          // [128]

    const int tid  = threadIdx.x;
    const int warp = tid >> 5, lane = tid & 31;
    const int g  = lane >> 2, t4 = lane & 3;
    const int wm = warp >> 2, wn = warp & 3;   // 2m x 4n, warp tile 64x32
    const int m0 = blockIdx.x * 128;

    if (tid < 128) bias[tid] = (tid < NS) ? ba[tid] : bb[tid - NS];

    // this thread's 4 chunks: row = c>>3, col4 = (c&7)*4  (perfectly coalesced)
    int rows[4], cols[4];
    #pragma unroll
    for (int j = 0; j < 4; j++) {
        int c = tid + j * 256;
        rows[j] = c >> 3;
        cols[j] = (c & 7) * 4;
    }

    float acc[4][4][4];
    #pragma unroll
    for (int i = 0; i < 4; i++)
        #pragma unroll
        for (int j = 0; j < 4; j++)
            #pragma unroll
            for (int k = 0; k < 4; k++) acc[i][j][k] = 0.f;

    float4 xr[4], wr[4];
    auto load_regs = [&](int k0) {
        #pragma unroll
        for (int j = 0; j < 4; j++) {
            xr[j] = *(const float4*)&x[(size_t)(m0 + rows[j])*ND + k0 + cols[j]];
            const float* wsrc = (rows[j] < NS)
                ? &Wa[(size_t)rows[j]*ND + k0 + cols[j]]
                : &Wb[(size_t)(rows[j] - NS)*ND + k0 + cols[j]];
            wr[j] = *(const float4*)wsrc;
        }
    };
    auto store_regs = [&](int buf) {
        #pragma unroll
        for (int j = 0; j < 4; j++) {
            uint2 xv = make_uint2(pack_h2(xr[j].x, xr[j].y),
                                  pack_h2(xr[j].z, xr[j].w));
            uint2 wv = make_uint2(pack_h2(wr[j].x, wr[j].y),
                                  pack_h2(wr[j].z, wr[j].w));
            *(uint2*)&Xh[(buf*128 + rows[j])*LDXH + cols[j]] = xv;
            *(uint2*)&Wh[(buf*128 + rows[j])*LDXH + cols[j]] = wv;
        }
    };

    const int KT = ND / BK1;   // 64
    load_regs(0);
    for (int kt = 0; kt < KT; kt++) {
        const int cur = kt & 1;
        store_regs(cur);
        __syncthreads();
        if (kt + 1 < KT) load_regs((kt + 1) * BK1);   // overlaps mma below

        const __half* Xc = &Xh[cur * 128 * LDXH];
        const __half* Wc = &Wh[cur * 128 * LDXH];
        #pragma unroll
        for (int kk = 0; kk < 2; kk++) {       // two K=16 steps per BK=32
            const int cb = kk*16 + 2*t4;
            unsigned int af[4][4];
            #pragma unroll
            for (int im = 0; im < 4; im++) {
                int r = wm*64 + im*16 + g;
                af[im][0] = *(const unsigned int*)&Xc[r*LDXH + cb];
                af[im][1] = *(const unsigned int*)&Xc[(r+8)*LDXH + cb];
                af[im][2] = *(const unsigned int*)&Xc[r*LDXH + cb + 8];
                af[im][3] = *(const unsigned int*)&Xc[(r+8)*LDXH + cb + 8];
            }
            unsigned int bf[4][2];
            #pragma unroll
            for (int in = 0; in < 4; in++) {
                int n = wn*32 + in*8 + g;
                bf[in][0] = *(const unsigned int*)&Wc[n*LDXH + cb];
                bf[in][1] = *(const unsigned int*)&Wc[n*LDXH + cb + 8];
            }
            #pragma unroll
            for (int im = 0; im < 4; im++)
                #pragma unroll
                for (int in = 0; in < 4; in++)
                    mma16h(acc[im][in], af[im], bf[in]);
        }
        __syncthreads();
    }

    // Epilogue: + bias, tanh, split store to g_a (cols<64) / g_b (cols>=64)
    float* dst = (wn >= 2) ? g_b : g_a;
    #pragma unroll
    for (int im = 0; im < 4; im++) {
        #pragma unroll
        for (int in = 0; in < 4; in++) {
            int ncol = wn*32 + in*8 + 2*t4;       // global col 0..127
            float b0v = bias[ncol], b1v = bias[ncol + 1];
            int cl = (wn & 1)*32 + in*8 + 2*t4;   // local col within 64
            size_t r0 = (size_t)(m0 + wm*64 + im*16 + g);
            float2 v0 = make_float2(tanhf(acc[im][in][0] + b0v),
                                    tanhf(acc[im][in][1] + b1v));
            float2 v1 = make_float2(tanhf(acc[im][in][2] + b0v),
                                    tanhf(acc[im][in][3] + b1v));
            *(float2*)&g_a[0] ;  // (no-op guard removed below)
            *(float2*)&dst[r0*NS + cl]       = v0;
            *(float2*)&dst[(r0+8)*NS + cl]   = v1;
        }
    }
}

// ---------------- kernel 2: chunked affine scan over T --------------------
__global__ void __launch_bounds__(256)
scan1_kernel() {
    __shared__ float As[CLEN*NS];   // 16 KB
    __shared__ float Bs[CLEN*NS];   // 16 KB
    const int c = blockIdx.x, b = blockIdx.y;
    size_t base = ((size_t)b * NT + (size_t)c * CLEN) * NS;

    #pragma unroll
    for (int j = 0; j < 4; j++) {
        int idx = (threadIdx.x + j * 256) * 4;
        cpa16(&As[idx], &g_a[base + idx]);
        cpa16(&Bs[idx], &g_b[base + idx]);
    }
    cp_commit();
    asm volatile("cp.async.wait_group 0;" ::: "memory");
    __syncthreads();

    if (threadIdx.x < NS) {
        const int s = threadIdx.x;
        float A = 1.f, E = 0.f;
        #pragma unroll 16
        for (int t = 0; t < CLEN; t++) {
            float av = As[t*NS + s];
            float bv = Bs[t*NS + s];
            E = fmaf(av, E, bv);
            A *= av;
        }
        int o = (b * NCHUNK + c) * NS + s;
        g_A[o] = A;
        g_E[o] = E;
    }
}

__global__ void __launch_bounds__(64)
scan2_kernel() {
    __shared__ float As[NCHUNK][NS];
    __shared__ float Es[NCHUNK][NS];
    const int b = blockIdx.x, s = threadIdx.x;

    #pragma unroll
    for (int c = 0; c < NCHUNK; c++) {
        int o = (b * NCHUNK + c) * NS + s;
        As[c][s] = g_A[o];
        Es[c][s] = g_E[o];
    }
    __syncthreads();

    float h = 0.f;
    #pragma unroll
    for (int c = 0; c < NCHUNK; c++) {
        g_hin[(b * NCHUNK + c) * NS + s] = h;
        h = fmaf(As[c][s], h, Es[c][s]);
    }
}

__global__ void __launch_bounds__(256)
scan3_kernel() {
    __shared__ float As[CLEN*NS];   // 16 KB
    __shared__ float Bs[CLEN*NS];   // 16 KB
    const int c = blockIdx.x, b = blockIdx.y;
    size_t base = ((size_t)b * NT + (size_t)c * CLEN) * NS;

    #pragma unroll
    for (int j = 0; j < 4; j++) {
        int idx = (threadIdx.x + j * 256) * 4;
        cpa16(&As[idx], &g_a[base + idx]);
        cpa16(&Bs[idx], &g_b[base + idx]);
    }
    cp_commit();
    asm volatile("cp.async.wait_group 0;" ::: "memory");
    __syncthreads();

    if (threadIdx.x < 32) {
        const int s = threadIdx.x * 2;
        float2 h = *(const float2*)&g_hin[(b * NCHUNK + c) * NS + s];
        #pragma unroll 16
        for (int t = 0; t < CLEN; t++) {
            float2 av = *(const float2*)&As[t*NS + s];
            float2 bv = *(const float2*)&Bs[t*NS + s];
            h.x = fmaf(av.x, h.x, bv.x);
            h.y = fmaf(av.y, h.y, bv.y);
            *(__half2*)&g_hs[base + t*NS + s] = __floats2half2_rn(h.x, h.y);
        }
    }
}

// ---------------- kernel 3: out = x + hs @ Wout^T + bout ------------------
// GEMM M=32768, N=2048, K=64, fp16 m16n8k16 (hs fp16, Wout packed at load).
#define LDH3 72
#define LDW3 72

__global__ void __launch_bounds__(256, 4)
out_kernel(const float* __restrict__ x, const float* __restrict__ Wout,
           const float* __restrict__ bout, float* __restrict__ out) {
    extern __shared__ char sm[];
    __half* Hs = (__half*)sm;                                 // [128][LDH3]
    float*  Ws = (float*)(sm + 128*LDH3*2);                   // [64][LDW3]
    float*  bs = (float*)(sm + 128*LDH3*2 + 64*LDW3*4);       // [64]

    const int tid  = threadIdx.x;
    const int warp = tid >> 5, lane = tid & 31;
    const int g  = lane >> 2, t4 = lane & 3;
    const int wm = warp >> 1, wn = warp & 1;
    const int n0 = blockIdx.x * 64;
    const int m0 = blockIdx.y * 128;

    if (tid < 64) bs[tid] = bout[n0 + tid];

    #pragma unroll
    for (int j = 0; j < 4; j++) {            // Hs: 1024 chunks of 8 halves
        int c   = tid + j * 256;
        int row = c >> 3;
        int kc  = (c & 7) * 8;
        cpa16(&Hs[row*LDH3 + kc], &g_hs[(size_t)(m0 + row)*NS + kc]);
    }
    #pragma unroll
    for (int j = 0; j < 4; j++) {            // Ws: 1024 chunks of 4 floats
        int c   = tid + j * 256;
        int row = c >> 4;
        int kc  = (c & 15) * 4;
        cpa16(&Ws[row*LDW3 + kc], &Wout[(size_t)(n0 + row)*NS + kc]);
    }
    cp_commit();
    asm volatile("cp.async.wait_group 0;" ::: "memory");
    __syncthreads();

    float acc[2][4][4];
    #pragma unroll
    for (int i = 0; i < 2; i++)
        #pragma unroll
        for (int j = 0; j < 4; j++)
            #pragma unroll
            for (int k = 0; k < 4; k++) acc[i][j][k] = 0.f;

    #pragma unroll
    for (int kk = 0; kk < 4; kk++) {         // four K=16 steps
        const int cb = kk*16 + 2*t4;
        unsigned int af[2][4];
        #pragma unroll
        for (int im = 0; im < 2; im++) {
            int r = wm*32 + im*16 + g;
            af[im][0] = *(const unsigned int*)&Hs[r*LDH3 + cb];
            af[im][1] = *(const unsigned int*)&Hs[(r+8)*LDH3 + cb];
            af[im][2] = *(const unsigned int*)&Hs[r*LDH3 + cb + 8];
            af[im][3] = *(const unsigned int*)&Hs[(r+8)*LDH3 + cb + 8];
        }
        unsigned int bf[4][2];
        #pragma unroll
        for (int in = 0; in < 4; in++) {
            int n = wn*32 + in*8 + g;
            float2 q0 = *(const float2*)&Ws[n*LDW3 + cb];
            float2 q1 = *(const float2*)&Ws[n*LDW3 + cb + 8];
            bf[in][0] = pack_h2(q0.x, q0.y);
            bf[in][1] = pack_h2(q1.x, q1.y);
        }
        #pragma unroll
        for (int im = 0; im < 2; im++)
            #pragma unroll
            for (int in = 0; in < 4; in++)
                mma16h(acc[im][in], af[im], bf[in]);
    }

    #pragma unroll
    for (int im = 0; im < 2; im++) {
        #pragma unroll
        for (int in = 0; in < 4; in++) {
            int dl = wn*32 + in*8 + 2*t4;
            int d  = n0 + dl;
            float bo0 = bs[dl], bo1 = bs[dl + 1];
            size_t r0 = (size_t)(m0 + wm*32 + im*16 + g);
            float2 x0 = __ldcs((const float2*)&x[r0*ND + d]);
            float2 x1 = __ldcs((const float2*)&x[(r0+8)*ND + d]);
            float2 o0 = make_float2(acc[im][in][0] + x0.x + bo0,
                                    acc[im][in][1] + x0.y + bo1);
            float2 o1 = make_float2(acc[im][in][2] + x1.x + bo0,
                                    acc[im][in][3] + x1.y + bo1);
            __stcs((float2*)&out[r0*ND + d],     o0);
            __stcs((float2*)&out[(r0+8)*ND + d], o1);
        }
    }
}

// ---------------- launcher ------------------------------------------------
extern "C" void kernel_launch(void* const* d_in, const int* in_sizes, int n_in,
                              void* d_out, int out_size) {
    const float* x    = (const float*)d_in[0];
    const float* Wa   = (const float*)d_in[1];
    const float* ba   = (const float*)d_in[2];
    const float* Wb   = (const float*)d_in[3];
    const float* bb   = (const float*)d_in[4];
    const float* Wout = (const float*)d_in[5];
    const float* bout = (const float*)d_in[6];
    float* out = (float*)d_out;
    (void)in_sizes; (void)n_in; (void)out_size;

    const size_t sm1 = (size_t)4*128*LDXH*2 + 512;               // 41472 B
    const size_t sm3 = (size_t)128*LDH3*2 + 64*LDW3*4 + 256;     // 37120 B
    cudaFuncSetAttribute(proj_kernel, cudaFuncAttributeMaxDynamicSharedMemorySize,
                         (int)sm1);
    cudaFuncSetAttribute(out_kernel, cudaFuncAttributeMaxDynamicSharedMemorySize,
                         (int)sm3);

    // 1. projections + tanh (fp16 smem tiles, register-staged loads)
    proj_kernel<<<M_TOT / 128, 256, sm1>>>(x, Wa, Wb, ba, bb);

    // 2. chunked affine recurrence scan (3 phases, smem-staged chains)
    scan1_kernel<<<dim3(NCHUNK, NB), 256>>>();
    scan2_kernel<<<NB, 64>>>();
    scan3_kernel<<<dim3(NCHUNK, NB), 256>>>();

    // 3. output projection + residual (fp16 tensor path)
    out_kernel<<<dim3(ND / 64, M_TOT / 128), 256, sm3>>>(x, Wout, bout, out);
}

// round 15
// speedup vs baseline: 1.0102x; 1.0102x over previous
#include <cuda_runtime.h>
#include <cuda_fp16.h>

// Problem constants
#define NB 8
#define NT 4096
#define ND 2048
#define NS 64
#define M_TOT (NB*NT)      // 32768 rows
#define NCHUNK 64          // scan chunks
#define CLEN   64          // steps per chunk (NCHUNK*CLEN == NT)

// ---------------- scratch (static __device__ — no allocations allowed) ----
__device__ float        g_a[(size_t)M_TOT*NS];        // 8 MB  gate  (fp32)
__device__ float        g_b[(size_t)M_TOT*NS];        // 8 MB  input (fp32)
__device__ __half       g_hs[(size_t)M_TOT*NS];       // 4 MB  states (fp16)
__device__ float        g_A[(size_t)NB*NCHUNK*NS];    // chunk gate products
__device__ float        g_E[(size_t)NB*NCHUNK*NS];    // chunk local end values
__device__ float        g_hin[(size_t)NB*NCHUNK*NS];  // chunk entry states
__device__ int          g_cnt[NB];                    // publish counters
__device__ int          g_flag[NB];                   // hin-ready flags

// ---------------- helpers -------------------------------------------------
__device__ __forceinline__ void mma16h(float c[4], const unsigned int a[4],
                                       const unsigned int b[2]) {
    asm volatile(
        "mma.sync.aligned.m16n8k16.row.col.f32.f16.f16.f32 "
        "{%0,%1,%2,%3},{%4,%5,%6,%7},{%8,%9},{%0,%1,%2,%3};"
        : "+f"(c[0]), "+f"(c[1]), "+f"(c[2]), "+f"(c[3])
        : "r"(a[0]), "r"(a[1]), "r"(a[2]), "r"(a[3]), "r"(b[0]), "r"(b[1]));
}

__device__ __forceinline__ unsigned int pack_h2(float lo, float hi) {
    __half2 h = __floats2half2_rn(lo, hi);
    return *reinterpret_cast<unsigned int*>(&h);
}

__device__ __forceinline__ void cpa16(void* sdst, const void* gsrc) {
    unsigned int sa = (unsigned int)__cvta_generic_to_shared(sdst);
    asm volatile("cp.async.cg.shared.global [%0], [%1], 16;"
                 :: "r"(sa), "l"(gsrc) : "memory");
}
__device__ __forceinline__ void cp_commit() {
    asm volatile("cp.async.commit_group;" ::: "memory");
}

// ---------------- kernel 1: a,b = tanh(x @ [Wa;Wb]^T + bias) --------------
// GEMM M=32768, N=128, K=2048. 128x128 blocks, BK=32 double-buffered.
// 8 warps in 2(m) x 4(n) grid, warp tile 64x32, fp16 m16n8k16 mma.
// fp32 smem tiles via cp.async; fragments packed to half2 at load (R12).
#define BK1  32
#define LDA1 40

__global__ void __launch_bounds__(256, 2)
proj_kernel(const float* __restrict__ x,
            const float* __restrict__ Wa, const float* __restrict__ Wb,
            const float* __restrict__ ba, const float* __restrict__ bb) {
    extern __shared__ char sm[];
    float*        Xs   = (float*)sm;                          // [2][128][LDA1]
    float*        Ws   = (float*)(sm + 2*128*LDA1*4);         // [2][128][LDA1]
    float*        bias = (float*)(sm + 4*128*LDA1*4);         // [128]

    const int tid  = threadIdx.x;
    const int warp = tid >> 5, lane = tid & 31;
    const int g  = lane >> 2, t4 = lane & 3;
    const int wm = warp >> 2, wn = warp & 3;   // 2m x 4n, warp tile 64x32
    const int m0 = blockIdx.x * 128;

    // zero the scan-phase sync state (stream order puts this before scan)
    if (blockIdx.x == 0 && tid < NB) {
        g_cnt[tid]  = 0;
        g_flag[tid] = 0;
    }

    if (tid < 128) bias[tid] = (tid < NS) ? ba[tid] : bb[tid - NS];

    float acc[4][4][4];
    #pragma unroll
    for (int i = 0; i < 4; i++)
        #pragma unroll
        for (int j = 0; j < 4; j++)
            #pragma unroll
            for (int k = 0; k < 4; k++) acc[i][j][k] = 0.f;

    auto issue = [&](int buf, int k0) {
        #pragma unroll
        for (int j = 0; j < 4; j++) {
            int c   = tid + j * 256;       // 1024 chunks of 4 floats
            int row = c >> 3;              // 8 chunks per 32-wide row
            int kc  = (c & 7) * 4;
            cpa16(&Xs[(buf*128 + row)*LDA1 + kc],
                  &x[(size_t)(m0 + row)*ND + k0 + kc]);
            const float* wsrc = (row < NS)
                ? &Wa[(size_t)row*ND + k0 + kc]
                : &Wb[(size_t)(row - NS)*ND + k0 + kc];
            cpa16(&Ws[(buf*128 + row)*LDA1 + kc], wsrc);
        }
        cp_commit();
    };

    issue(0, 0);
    const int KT = ND / BK1;   // 64
    for (int kt = 0; kt < KT; kt++) {
        const int cur = kt & 1;
        if (kt + 1 < KT) {
            issue(cur ^ 1, (kt + 1) * BK1);
            asm volatile("cp.async.wait_group 1;" ::: "memory");
        } else {
            asm volatile("cp.async.wait_group 0;" ::: "memory");
        }
        __syncthreads();

        const float* Xc = &Xs[cur * 128 * LDA1];
        const float* Wc = &Ws[cur * 128 * LDA1];
        #pragma unroll
        for (int kk = 0; kk < 2; kk++) {       // two K=16 steps per BK=32
            const int cb = kk*16 + 2*t4;
            unsigned int af[4][4];
            #pragma unroll
            for (int im = 0; im < 4; im++) {
                int r = wm*64 + im*16 + g;
                float2 p0 = *(const float2*)&Xc[r*LDA1 + cb];
                float2 p1 = *(const float2*)&Xc[(r+8)*LDA1 + cb];
                float2 p2 = *(const float2*)&Xc[r*LDA1 + cb + 8];
                float2 p3 = *(const float2*)&Xc[(r+8)*LDA1 + cb + 8];
                af[im][0] = pack_h2(p0.x, p0.y);
                af[im][1] = pack_h2(p1.x, p1.y);
                af[im][2] = pack_h2(p2.x, p2.y);
                af[im][3] = pack_h2(p3.x, p3.y);
            }
            unsigned int bf[4][2];
            #pragma unroll
            for (int in = 0; in < 4; in++) {
                int n = wn*32 + in*8 + g;
                float2 q0 = *(const float2*)&Wc[n*LDA1 + cb];
                float2 q1 = *(const float2*)&Wc[n*LDA1 + cb + 8];
                bf[in][0] = pack_h2(q0.x, q0.y);
                bf[in][1] = pack_h2(q1.x, q1.y);
            }
            #pragma unroll
            for (int im = 0; im < 4; im++)
                #pragma unroll
                for (int in = 0; in < 4; in++)
                    mma16h(acc[im][in], af[im], bf[in]);
        }
        __syncthreads();
    }

    // Epilogue: + bias, tanh, split store to g_a (cols<64) / g_b (cols>=64)
    float* dst = (wn >= 2) ? g_b : g_a;
    #pragma unroll
    for (int im = 0; im < 4; im++) {
        #pragma unroll
        for (int in = 0; in < 4; in++) {
            int ncol = wn*32 + in*8 + 2*t4;       // global col 0..127
            float b0v = bias[ncol], b1v = bias[ncol + 1];
            int cl = (wn & 1)*32 + in*8 + 2*t4;   // local col within 64
            size_t r0 = (size_t)(m0 + wm*64 + im*16 + g);
            float2 v0 = make_float2(tanhf(acc[im][in][0] + b0v),
                                    tanhf(acc[im][in][1] + b1v));
            float2 v1 = make_float2(tanhf(acc[im][in][2] + b0v),
                                    tanhf(acc[im][in][3] + b1v));
            *(float2*)&dst[r0*NS + cl]       = v0;
            *(float2*)&dst[(r0+8)*NS + cl]   = v1;
        }
    }
}

// ---------------- kernel 2: fused chunked affine scan ---------------------
// One launch. Per (b,c) CTA: stage slab once, compute (A,E), publish
// (fence + counter). CTA (b,0): replay chunk 0 immediately (h0 = 0), wait
// for all 64 publishes, combine out of reused smem, release flag. Others:
// spin on flag, replay from the still-resident slab.
// 33KB smem -> ~6 CTAs/SM -> all 512 CTAs co-resident (spin-safe).
__global__ void __launch_bounds__(256)
scan_fused_kernel() {
    __shared__ float As[CLEN*NS];   // 16 KB
    __shared__ float Bs[CLEN*NS];   // 16 KB
    const int c = blockIdx.x, b = blockIdx.y;
    const int tid = threadIdx.x;
    size_t base = ((size_t)b * NT + (size_t)c * CLEN) * NS;

    #pragma unroll
    for (int j = 0; j < 4; j++) {
        int idx = (tid + j * 256) * 4;
        cpa16(&As[idx], &g_a[base + idx]);
        cpa16(&Bs[idx], &g_b[base + idx]);
    }
    cp_commit();
    asm volatile("cp.async.wait_group 0;" ::: "memory");
    __syncthreads();

    // Phase 1: per-chunk (A, E)
    if (tid < NS) {
        float A = 1.f, E = 0.f;
        #pragma unroll 16
        for (int t = 0; t < CLEN; t++) {
            float av = As[t*NS + tid];
            float bv = Bs[t*NS + tid];
            E = fmaf(av, E, bv);
            A *= av;
        }
        int o = (b * NCHUNK + c) * NS + tid;
        g_A[o] = A;
        g_E[o] = E;
    }
    __threadfence();
    __syncthreads();
    if (tid == 0) atomicAdd(&g_cnt[b], 1);

    if (c == 0) {
        // replay chunk 0 right away (entry state is exactly 0)
        if (tid < 32) {
            const int s = tid * 2;
            float2 h = make_float2(0.f, 0.f);
            #pragma unroll 16
            for (int t = 0; t < CLEN; t++) {
                float2 av = *(const float2*)&As[t*NS + s];
                float2 bv = *(const float2*)&Bs[t*NS + s];
                h.x = fmaf(av.x, h.x, bv.x);
                h.y = fmaf(av.y, h.y, bv.y);
                *(__half2*)&g_hs[base + t*NS + s] = __floats2half2_rn(h.x, h.y);
            }
        }
        if (tid == 0) {
            while (atomicAdd(&g_cnt[b], 0) < NCHUNK) {}
        }
        __syncthreads();
        __threadfence();
        // stage (A, E) of all 64 chunks into reused smem (slab now dead)
        #pragma unroll
        for (int j = 0; j < 16; j++) {
            int idx = tid + j * 256;           // 4096 entries
            As[idx] = g_A[b * NCHUNK * NS + idx];
            Bs[idx] = g_E[b * NCHUNK * NS + idx];
        }
        __syncthreads();
        if (tid < NS) {
            float h = 0.f;
            #pragma unroll
            for (int cc = 0; cc < NCHUNK; cc++) {
                g_hin[(b * NCHUNK + cc) * NS + tid] = h;
                h = fmaf(As[cc*NS + tid], h, Bs[cc*NS + tid]);
            }
        }
        __threadfence();
        __syncthreads();
        if (tid == 0) atomicExch(&g_flag[b], 1);
    } else {
        if (tid == 0) {
            while (atomicAdd(&g_flag[b], 0) == 0) {}
        }
        __syncthreads();
        __threadfence();
        if (tid < 32) {
            const int s = tid * 2;
            float2 h = *(const float2*)&g_hin[(b * NCHUNK + c) * NS + s];
            #pragma unroll 16
            for (int t = 0; t < CLEN; t++) {
                float2 av = *(const float2*)&As[t*NS + s];
                float2 bv = *(const float2*)&Bs[t*NS + s];
                h.x = fmaf(av.x, h.x, bv.x);
                h.y = fmaf(av.y, h.y, bv.y);
                *(__half2*)&g_hs[base + t*NS + s] = __floats2half2_rn(h.x, h.y);
            }
        }
    }
}

// ---------------- kernel 3: out = x + hs @ Wout^T + bout ------------------
// GEMM M=32768, N=2048, K=64, fp16 m16n8k16 (hs fp16, Wout packed at load).
#define LDH3 72
#define LDW3 72

__global__ void __launch_bounds__(256, 4)
out_kernel(const float* __restrict__ x, const float* __restrict__ Wout,
           const float* __restrict__ bout, float* __restrict__ out) {
    extern __shared__ char sm[];
    __half* Hs = (__half*)sm;                                 // [128][LDH3]
    float*  Ws = (float*)(sm + 128*LDH3*2);                   // [64][LDW3]
    float*  bs = (float*)(sm + 128*LDH3*2 + 64*LDW3*4);       // [64]

    const int tid  = threadIdx.x;
    const int warp = tid >> 5, lane = tid & 31;
    const int g  = lane >> 2, t4 = lane & 3;
    const int wm = warp >> 1, wn = warp & 1;
    const int n0 = blockIdx.x * 64;
    const int m0 = blockIdx.y * 128;

    if (tid < 64) bs[tid] = bout[n0 + tid];

    #pragma unroll
    for (int j = 0; j < 4; j++) {            // Hs: 1024 chunks of 8 halves
        int c   = tid + j * 256;
        int row = c >> 3;
        int kc  = (c & 7) * 8;
        cpa16(&Hs[row*LDH3 + kc], &g_hs[(size_t)(m0 + row)*NS + kc]);
    }
    #pragma unroll
    for (int j = 0; j < 4; j++) {            // Ws: 1024 chunks of 4 floats
        int c   = tid + j * 256;
        int row = c >> 4;
        int kc  = (c & 15) * 4;
        cpa16(&Ws[row*LDW3 + kc], &Wout[(size_t)(n0 + row)*NS + kc]);
    }
    cp_commit();
    asm volatile("cp.async.wait_group 0;" ::: "memory");
    __syncthreads();

    float acc[2][4][4];
    #pragma unroll
    for (int i = 0; i < 2; i++)
        #pragma unroll
        for (int j = 0; j < 4; j++)
            #pragma unroll
            for (int k = 0; k < 4; k++) acc[i][j][k] = 0.f;

    #pragma unroll
    for (int kk = 0; kk < 4; kk++) {         // four K=16 steps
        const int cb = kk*16 + 2*t4;
        unsigned int af[2][4];
        #pragma unroll
        for (int im = 0; im < 2; im++) {
            int r = wm*32 + im*16 + g;
            af[im][0] = *(const unsigned int*)&Hs[r*LDH3 + cb];
            af[im][1] = *(const unsigned int*)&Hs[(r+8)*LDH3 + cb];
            af[im][2] = *(const unsigned int*)&Hs[r*LDH3 + cb + 8];
            af[im][3] = *(const unsigned int*)&Hs[(r+8)*LDH3 + cb + 8];
        }
        unsigned int bf[4][2];
        #pragma unroll
        for (int in = 0; in < 4; in++) {
            int n = wn*32 + in*8 + g;
            float2 q0 = *(const float2*)&Ws[n*LDW3 + cb];
            float2 q1 = *(const float2*)&Ws[n*LDW3 + cb + 8];
            bf[in][0] = pack_h2(q0.x, q0.y);
            bf[in][1] = pack_h2(q1.x, q1.y);
        }
        #pragma unroll
        for (int im = 0; im < 2; im++)
            #pragma unroll
            for (int in = 0; in < 4; in++)
                mma16h(acc[im][in], af[im], bf[in]);
    }

    #pragma unroll
    for (int im = 0; im < 2; im++) {
        #pragma unroll
        for (int in = 0; in < 4; in++) {
            int dl = wn*32 + in*8 + 2*t4;
            int d  = n0 + dl;
            float bo0 = bs[dl], bo1 = bs[dl + 1];
            size_t r0 = (size_t)(m0 + wm*32 + im*16 + g);
            float2 x0 = __ldcs((const float2*)&x[r0*ND + d]);
            float2 x1 = __ldcs((const float2*)&x[(r0+8)*ND + d]);
            float2 o0 = make_float2(acc[im][in][0] + x0.x + bo0,
                                    acc[im][in][1] + x0.y + bo1);
            float2 o1 = make_float2(acc[im][in][2] + x1.x + bo0,
                                    acc[im][in][3] + x1.y + bo1);
            __stcs((float2*)&out[r0*ND + d],     o0);
            __stcs((float2*)&out[(r0+8)*ND + d], o1);
        }
    }
}

// ---------------- launcher ------------------------------------------------
extern "C" void kernel_launch(void* const* d_in, const int* in_sizes, int n_in,
                              void* d_out, int out_size) {
    const float* x    = (const float*)d_in[0];
    const float* Wa   = (const float*)d_in[1];
    const float* ba   = (const float*)d_in[2];
    const float* Wb   = (const float*)d_in[3];
    const float* bb   = (const float*)d_in[4];
    const float* Wout = (const float*)d_in[5];
    const float* bout = (const float*)d_in[6];
    float* out = (float*)d_out;
    (void)in_sizes; (void)n_in; (void)out_size;

    const size_t sm1 = (size_t)4*128*LDA1*4 + 512;               // 82432 B
    const size_t sm3 = (size_t)128*LDH3*2 + 64*LDW3*4 + 256;     // 37120 B
    cudaFuncSetAttribute(proj_kernel, cudaFuncAttributeMaxDynamicSharedMemorySize,
                         (int)sm1);
    cudaFuncSetAttribute(out_kernel, cudaFuncAttributeMaxDynamicSharedMemorySize,
                         (int)sm3);

    // 1. projections + tanh (fp16 tensor path; also zeroes scan sync state)
    proj_kernel<<<M_TOT / 128, 256, sm1>>>(x, Wa, Wb, ba, bb);

    // 2. fused chunked affine recurrence scan (single launch, spin-synced)
    scan_fused_kernel<<<dim3(NCHUNK, NB), 256>>>();

    // 3. output projection + residual (fp16 tensor path)
    out_kernel<<<dim3(ND / 64, M_TOT / 128), 256, sm3>>>(x, Wout, bout, out);
}